// round 16
// baseline (speedup 1.0000x reference)
#include <cuda_runtime.h>
#include <cstdint>

// Problem constants
static constexpr int N_ = 1024;
static constexpr int K_ = 32;
static constexpr int I_ = 10000;
static constexpr int I4_ = I_ / 4;       // 2500 float4 chunks per row

static constexpr float CS_  = 0.43280850f;     // 3/(10*ln2)
// CB4 = 51.2+25.6+12.7 (magic-number rebase + exp-bias consts)
//     + 0.0528766 (-0.1*log2(ln2)) + 0.0653382 (deg-2 poly C, balanced)
static constexpr float CB4_ = 89.6182148f;

// Precomputed per-(k,i) score base: sc = CS*logits + CB4  (1.28 MB, L2-resident)
__device__ float g_sc[K_ * I_];

__device__ __forceinline__ float lg2_approx(float v) {
    float r; asm("lg2.approx.f32 %0, %1;" : "=f"(r) : "f"(v)); return r;
}
__device__ __forceinline__ float ex2_approx(float v) {
    float r; asm("ex2.approx.f32 %0, %1;" : "=f"(r) : "f"(v)); return r;
}
// f32x2 packed helpers (sm_103a FFMA2 path — ptxas never emits these from C++)
__device__ __forceinline__ uint64_t pk(float lo, float hi) {
    uint64_t r; asm("mov.b64 %0, {%1, %2};" : "=l"(r) : "f"(lo), "f"(hi)); return r;
}
__device__ __forceinline__ void upk(uint64_t v, float& lo, float& hi) {
    asm("mov.b64 {%0, %1}, %2;" : "=f"(lo), "=f"(hi) : "l"(v));
}
__device__ __forceinline__ uint64_t fma2(uint64_t a, uint64_t b, uint64_t c) {
    uint64_t d; asm("fma.rn.f32x2 %0, %1, %2, %3;" : "=l"(d) : "l"(a), "l"(b), "l"(c)); return d;
}
__device__ __forceinline__ uint64_t add2(uint64_t a, uint64_t b) {
    uint64_t d; asm("add.rn.f32x2 %0, %1, %2;" : "=l"(d) : "l"(a), "l"(b)); return d;
}

__global__ void precompute_sc_kernel(const float* __restrict__ logits) {
    int i = blockIdx.x * blockDim.x + threadIdx.x;
    if (i < (K_ * I_) / 4) {
        float4 v = reinterpret_cast<const float4*>(logits)[i];
        v.x = fmaf(v.x, CS_, CB4_);
        v.y = fmaf(v.y, CS_, CB4_);
        v.z = fmaf(v.z, CS_, CB4_);
        v.w = fmaf(v.w, CS_, CB4_);
        reinterpret_cast<float4*>(g_sc)[i] = v;
    }
}

// out[n,k] = (sum_i x*w) / (sum_i w),   w = 2^score,
// score = sc - 0.1*log2(-ln u) (sc holds logits term + every additive const).
//
// With L = lg2(u) (<0), b = bits(L): the exponent part of the score comes
// from the magic-number float view f = uint_as_float((b>>9)|0x4B000000)
// = 2^23 + b/512 exactly, folded into sc by one scalar FFMA. Mantissa
// correction -0.1*(log2 m - (m-1)) is a DEGREE-2 balanced-minimax poly
// A m^2 + B m (+C folded into sc): max score error 4.9e-4 (error-balanced at
// m=1 / m=2), i.e. <=3.4e-4 per-weight — the common component cancels in the
// softmax ratio, leaving ~2e-4 rms on the output. One fewer FFMA2 per pair
// and a 4-cycle shorter chain than the deg-3 version. IMNMX.U32 clamp on b
// (-L >= 2^-27) guards lg2.approx underflow at u->1 (m==1 there).
//
// Layout: mode-W (1 CTA x 1024 threads/SM). Zero-rotation ping-pong pipeline
// (prefetch distance 2, register-resident). Prologue LDGs issue BEFORE the
// x-staging loop so the first DRAM round-trip hides behind staging+barrier.
__global__ void __launch_bounds__(1024, 1)
concrete_selector_kernel(const float* __restrict__ x,
                         const float* __restrict__ u,
                         float* __restrict__ out) {
    __shared__ __align__(16) float xs[I_];   // x row for this n (40000 B)

    const int n   = blockIdx.x;
    const int tid = threadIdx.x;
    const int warp = tid >> 5;
    const int lane = tid & 31;
    const int k    = warp;    // 32 warps == 32 k's

    const float4* __restrict__ ug4 =
        reinterpret_cast<const float4*>(u + ((size_t)n * K_ + k) * (size_t)I_);
    const float4* __restrict__ cg4 =
        reinterpret_cast<const float4*>(g_sc + (size_t)k * I_);

    // Prologue loads FIRST — their latency hides behind x staging + barrier
    float4 PA = __ldcs(&ug4[lane]);
    float4 PC = cg4[lane];
    float4 QA = __ldcs(&ug4[lane + 32]);
    float4 QC = cg4[lane + 32];

    // Cooperative load of x[n, :] into shared (float4)
    {
        const float4* __restrict__ xg4 =
            reinterpret_cast<const float4*>(x + (size_t)n * I_);
        float4* xs4 = reinterpret_cast<float4*>(xs);
        for (int i = tid; i < I4_; i += 1024) xs4[i] = xg4[i];
    }
    __syncthreads();

    const ulonglong2* __restrict__ xsv =
        reinterpret_cast<const ulonglong2*>(xs);   // LDS.128 -> two packed pairs

    // Packed deg-2 poly: -0.1*(log2 m-(m-1)) ~= A m^2 + B m (+C in sc)
    const uint64_t PA2 = pk( 3.34036e-2f,  3.34036e-2f);
    const uint64_t PB2 = pk(-9.92330e-2f, -9.92330e-2f);

    uint64_t accA2 = 0;   // packed pair of partial sums of x*w
    uint64_t accB2 = 0;   // packed pair of partial sums of w

    auto ppair = [&](float u0, float u1, float sc0, float sc1, uint64_t xp) {
        float L0 = lg2_approx(u0);                 // XU (u<1 -> L<0)
        float L1 = lg2_approx(u1);
        unsigned b0 = __float_as_uint(L0);
        unsigned b1 = __float_as_uint(L1);
        b0 = b0 > 0xB2000000u ? b0 : 0xB2000000u;  // IMNMX.U32: -L >= 2^-27
        b1 = b1 > 0xB2000000u ? b1 : 0xB2000000u;
        float m0 = __int_as_float((b0 & 0x007fffffu) | 0x3f800000u);  // LOP3
        float m1 = __int_as_float((b1 & 0x007fffffu) | 0x3f800000u);
        float f0 = __uint_as_float((b0 >> 9) | 0x4B000000u);  // SHF+LOP3
        float f1 = __uint_as_float((b1 >> 9) | 0x4B000000u);
        float sv0 = fmaf(f0, -6.1035156e-6f, sc0); // scalar: short per-lane chain
        float sv1 = fmaf(f1, -6.1035156e-6f, sc1);
        uint64_t mp = pk(m0, m1);
        uint64_t r  = fma2(mp, PA2, PB2);
        uint64_t s2 = fma2(mp, r, pk(sv0, sv1));   // full log2-score (pair)
        float s0, s1; upk(s2, s0, s1);
        uint64_t wp = pk(ex2_approx(s0), ex2_approx(s1));   // XU x2
        accB2 = add2(accB2, wp);
        accA2 = fma2(xp, wp, accA2);
    };

    // 78 iterations per warp (chunks 0..2495). Ping-pong, prefetch distance 2:
    // consume P (chunk j), refill P from j+64; consume Q (j+32), refill from
    // j+96. No buffer rotation — no inter-buffer register moves.
    int j = lane;
    for (int it = 0; it < 38; ++it) {    // 38 * 2 = iterations 0..75
        ulonglong2 X = xsv[j];
        ppair(PA.x, PA.y, PC.x, PC.y, X.x);
        ppair(PA.z, PA.w, PC.z, PC.w, X.y);
        PA = __ldcs(&ug4[j + 64]);       // refill P for iteration it*2+2
        PC = cg4[j + 64];
        ulonglong2 X2 = xsv[j + 32];
        ppair(QA.x, QA.y, QC.x, QC.y, X2.x);
        ppair(QA.z, QA.w, QC.z, QC.w, X2.y);
        QA = __ldcs(&ug4[j + 96]);       // refill Q for iteration it*2+3
        QC = cg4[j + 96];
        j += 64;
    }
    // Epilogue: iterations 76, 77 are resident in P and Q (j = lane+2432)
    {
        ulonglong2 X = xsv[j];
        ppair(PA.x, PA.y, PC.x, PC.y, X.x);
        ppair(PA.z, PA.w, PC.z, PC.w, X.y);
        ulonglong2 X2 = xsv[j + 32];
        ppair(QA.x, QA.y, QC.x, QC.y, X2.x);
        ppair(QA.z, QA.w, QC.z, QC.w, X2.y);
    }
    // Tail: chunks 2496..2499 handled by lanes 0..3
    if (lane < I4_ - 2496) {
        int jt = 2496 + lane;
        float4 uu = __ldcs(&ug4[jt]);
        float4 cc = cg4[jt];
        ulonglong2 X = xsv[jt];
        ppair(uu.x, uu.y, cc.x, cc.y, X.x);
        ppair(uu.z, uu.w, cc.z, cc.w, X.y);
    }

    // Collapse packed accumulators, then warp reduction
    float a0, a1, bb0, bb1;
    upk(accA2, a0, a1);
    upk(accB2, bb0, bb1);
    float accA = a0 + a1;
    float accB = bb0 + bb1;
    #pragma unroll
    for (int off = 16; off > 0; off >>= 1) {
        accA += __shfl_down_sync(0xffffffffu, accA, off);
        accB += __shfl_down_sync(0xffffffffu, accB, off);
    }
    if (lane == 0) {
        out[(size_t)n * K_ + k] = accA / accB;
    }
}

extern "C" void kernel_launch(void* const* d_in, const int* in_sizes, int n_in,
                              void* d_out, int out_size) {
    const float* x      = (const float*)d_in[0];   // (1024, 10000)
    const float* u      = (const float*)d_in[1];   // (1024, 32, 10000)
    const float* logits = (const float*)d_in[2];   // (32, 10000)
    float* out = (float*)d_out;                    // (1024, 32)
    (void)in_sizes; (void)n_in; (void)out_size;

    // Stage 1: fold logits scaling + all additive constants into g_sc
    precompute_sc_kernel<<<(K_ * I_ / 4 + 255) / 256, 256>>>(logits);
    // Stage 2: main reduction
    concrete_selector_kernel<<<N_, 1024>>>(x, u, out);
}

// round 17
// speedup vs baseline: 1.0354x; 1.0354x over previous
#include <cuda_runtime.h>
#include <cstdint>

// ============================================================================
// FINAL (locked): Round-9 structure — empirical optimum at ~214 us.
// The session bracketed this point from every direction:
//   MORE instructions (R5-R8 bodies):        230-255 us (issue-bound)
//   FEWER instructions (R16 deg-2 poly):     223 us (latency-exposed: the
//       removed FFMA2s were hiding load latency, issue fell to 68.7% but
//       elapsed GREW)
//   multi-CTA (R4):                          393 us (cross-CTA L1tex spread)
//   cp.async ring (R11):                     262 us (commit/wait serialization)
//   prefetch depth 3 (R13):                  218 us (reg-cap, no MLP gain)
//   256-bit v8 loads (R14):                  226 us (L1tex wavefront amp.)
//   packed-sv / IMAD.HI (R10/R12):           217-218 us (chain / pipe mix)
// Equilibrium: issue ~72%, XU ~70%, DRAM ~77% — perturbations in any
// direction lose. rel_err 3.0e-4, stable across runs.
// ============================================================================

// Problem constants
static constexpr int N_ = 1024;
static constexpr int K_ = 32;
static constexpr int I_ = 10000;
static constexpr int I4_ = I_ / 4;       // 2500 float4 chunks per row

static constexpr float CS_  = 0.43280850f;     // 3/(10*ln2)
// CB3 = 51.2+25.6+12.7 (magic-number rebase + exp-bias consts)
//     + 0.0528766 (-0.1*log2(ln2)) + 0.1135508 (poly H0)
static constexpr float CB3_ = 89.6664274f;

// Precomputed per-(k,i) score base: sc = CS*logits + CB3  (1.28 MB, L2-resident)
__device__ float g_sc[K_ * I_];

__device__ __forceinline__ float lg2_approx(float v) {
    float r; asm("lg2.approx.f32 %0, %1;" : "=f"(r) : "f"(v)); return r;
}
__device__ __forceinline__ float ex2_approx(float v) {
    float r; asm("ex2.approx.f32 %0, %1;" : "=f"(r) : "f"(v)); return r;
}
// f32x2 packed helpers (sm_103a FFMA2 path — ptxas never emits these from C++)
__device__ __forceinline__ uint64_t pk(float lo, float hi) {
    uint64_t r; asm("mov.b64 %0, {%1, %2};" : "=l"(r) : "f"(lo), "f"(hi)); return r;
}
__device__ __forceinline__ void upk(uint64_t v, float& lo, float& hi) {
    asm("mov.b64 {%0, %1}, %2;" : "=f"(lo), "=f"(hi) : "l"(v));
}
__device__ __forceinline__ uint64_t fma2(uint64_t a, uint64_t b, uint64_t c) {
    uint64_t d; asm("fma.rn.f32x2 %0, %1, %2, %3;" : "=l"(d) : "l"(a), "l"(b), "l"(c)); return d;
}
__device__ __forceinline__ uint64_t add2(uint64_t a, uint64_t b) {
    uint64_t d; asm("add.rn.f32x2 %0, %1, %2;" : "=l"(d) : "l"(a), "l"(b)); return d;
}

__global__ void precompute_sc_kernel(const float* __restrict__ logits) {
    int i = blockIdx.x * blockDim.x + threadIdx.x;
    if (i < (K_ * I_) / 4) {
        float4 v = reinterpret_cast<const float4*>(logits)[i];
        v.x = fmaf(v.x, CS_, CB3_);
        v.y = fmaf(v.y, CS_, CB3_);
        v.z = fmaf(v.z, CS_, CB3_);
        v.w = fmaf(v.w, CS_, CB3_);
        reinterpret_cast<float4*>(g_sc)[i] = v;
    }
}

// out[n,k] = (sum_i x*w) / (sum_i w),   w = 2^score,
// score = sc - 0.1*log2(-ln u) (sc holds logits term + every additive const).
//
// With L = lg2(u) (<0), b = bits(L): the exponent part of the score comes
// from the magic-number float view f = uint_as_float((b>>9)|0x4B000000)
// = 2^23 + b/512 exactly, folded into sc by one scalar FFMA. Mantissa
// correction -0.1*(log2 m - (m-1)) is a packed degree-3 poly (FFMA2).
// IMNMX.U32 clamp on b (-L >= 2^-27) guards lg2.approx underflow at u->1
// (m==1.0 at the clamp so the poly term cancels).
//
// Layout: mode-W (1 CTA x 1024 threads/SM). Zero-rotation ping-pong pipeline
// (prefetch distance 2, register-resident); buffers refill in place — no
// inter-buffer register moves.
__global__ void __launch_bounds__(1024, 1)
concrete_selector_kernel(const float* __restrict__ x,
                         const float* __restrict__ u,
                         float* __restrict__ out) {
    __shared__ __align__(16) float xs[I_];   // x row for this n (40000 B)

    const int n   = blockIdx.x;
    const int tid = threadIdx.x;

    // Cooperative load of x[n, :] into shared (float4)
    {
        const float4* __restrict__ xg4 =
            reinterpret_cast<const float4*>(x + (size_t)n * I_);
        float4* xs4 = reinterpret_cast<float4*>(xs);
        for (int i = tid; i < I4_; i += 1024) xs4[i] = xg4[i];
    }
    __syncthreads();

    const int warp = tid >> 5;
    const int lane = tid & 31;
    const int k    = warp;    // 32 warps == 32 k's

    const float4* __restrict__ ug4 =
        reinterpret_cast<const float4*>(u + ((size_t)n * K_ + k) * (size_t)I_);
    const float4* __restrict__ cg4 =
        reinterpret_cast<const float4*>(g_sc + (size_t)k * I_);
    const ulonglong2* __restrict__ xsv =
        reinterpret_cast<const ulonglong2*>(xs);   // LDS.128 -> two packed pairs

    // Packed deg-3 poly: -0.1*(log2 m-(m-1)) ~= H3 m^3+H2 m^2+H1 m (+H0 in sc)
    const uint64_t H3 = pk(-1.52368e-2f,  -1.52368e-2f);
    const uint64_t H2 = pk( 1.025445e-1f,  1.025445e-1f);
    const uint64_t H1 = pk(-2.009419e-1f, -2.009419e-1f);

    uint64_t accA2 = 0;   // packed pair of partial sums of x*w
    uint64_t accB2 = 0;   // packed pair of partial sums of w

    auto ppair = [&](float u0, float u1, float sc0, float sc1, uint64_t xp) {
        float L0 = lg2_approx(u0);                 // XU (u<1 -> L<0)
        float L1 = lg2_approx(u1);
        unsigned b0 = __float_as_uint(L0);
        unsigned b1 = __float_as_uint(L1);
        b0 = b0 > 0xB2000000u ? b0 : 0xB2000000u;  // IMNMX.U32: -L >= 2^-27
        b1 = b1 > 0xB2000000u ? b1 : 0xB2000000u;
        float m0 = __int_as_float((b0 & 0x007fffffu) | 0x3f800000u);  // LOP3
        float m1 = __int_as_float((b1 & 0x007fffffu) | 0x3f800000u);
        float f0 = __uint_as_float((b0 >> 9) | 0x4B000000u);  // SHF+LOP3
        float f1 = __uint_as_float((b1 >> 9) | 0x4B000000u);
        float sv0 = fmaf(f0, -6.1035156e-6f, sc0); // scalar: short per-lane chain
        float sv1 = fmaf(f1, -6.1035156e-6f, sc1);
        uint64_t mp = pk(m0, m1);
        uint64_t r  = fma2(mp, H3, H2);
        r           = fma2(mp, r, H1);
        uint64_t s2 = fma2(mp, r, pk(sv0, sv1));   // full log2-score (pair)
        float s0, s1; upk(s2, s0, s1);
        uint64_t wp = pk(ex2_approx(s0), ex2_approx(s1));   // XU x2
        accB2 = add2(accB2, wp);
        accA2 = fma2(xp, wp, accA2);
    };

    // 78 iterations per warp (chunks 0..2495). Ping-pong, prefetch distance 2:
    // consume P (chunk j), refill P from j+64; consume Q (j+32), refill from
    // j+96. No buffer rotation — no inter-buffer register moves.
    float4 PA = __ldcs(&ug4[lane]);
    float4 PC = cg4[lane];
    float4 QA = __ldcs(&ug4[lane + 32]);
    float4 QC = cg4[lane + 32];
    int j = lane;
    for (int it = 0; it < 38; ++it) {    // 38 * 2 = iterations 0..75
        ulonglong2 X = xsv[j];
        ppair(PA.x, PA.y, PC.x, PC.y, X.x);
        ppair(PA.z, PA.w, PC.z, PC.w, X.y);
        PA = __ldcs(&ug4[j + 64]);       // refill P for iteration it*2+2
        PC = cg4[j + 64];
        ulonglong2 X2 = xsv[j + 32];
        ppair(QA.x, QA.y, QC.x, QC.y, X2.x);
        ppair(QA.z, QA.w, QC.z, QC.w, X2.y);
        QA = __ldcs(&ug4[j + 96]);       // refill Q for iteration it*2+3
        QC = cg4[j + 96];
        j += 64;
    }
    // Epilogue: iterations 76, 77 are resident in P and Q (j = lane+2432)
    {
        ulonglong2 X = xsv[j];
        ppair(PA.x, PA.y, PC.x, PC.y, X.x);
        ppair(PA.z, PA.w, PC.z, PC.w, X.y);
        ulonglong2 X2 = xsv[j + 32];
        ppair(QA.x, QA.y, QC.x, QC.y, X2.x);
        ppair(QA.z, QA.w, QC.z, QC.w, X2.y);
    }
    // Tail: chunks 2496..2499 handled by lanes 0..3
    if (lane < I4_ - 2496) {
        int jt = 2496 + lane;
        float4 uu = __ldcs(&ug4[jt]);
        float4 cc = cg4[jt];
        ulonglong2 X = xsv[jt];
        ppair(uu.x, uu.y, cc.x, cc.y, X.x);
        ppair(uu.z, uu.w, cc.z, cc.w, X.y);
    }

    // Collapse packed accumulators, then warp reduction
    float a0, a1, bb0, bb1;
    upk(accA2, a0, a1);
    upk(accB2, bb0, bb1);
    float accA = a0 + a1;
    float accB = bb0 + bb1;
    #pragma unroll
    for (int off = 16; off > 0; off >>= 1) {
        accA += __shfl_down_sync(0xffffffffu, accA, off);
        accB += __shfl_down_sync(0xffffffffu, accB, off);
    }
    if (lane == 0) {
        out[(size_t)n * K_ + k] = accA / accB;
    }
}

extern "C" void kernel_launch(void* const* d_in, const int* in_sizes, int n_in,
                              void* d_out, int out_size) {
    const float* x      = (const float*)d_in[0];   // (1024, 10000)
    const float* u      = (const float*)d_in[1];   // (1024, 32, 10000)
    const float* logits = (const float*)d_in[2];   // (32, 10000)
    float* out = (float*)d_out;                    // (1024, 32)
    (void)in_sizes; (void)n_in; (void)out_size;

    // Stage 1: fold logits scaling + all additive constants into g_sc
    precompute_sc_kernel<<<(K_ * I_ / 4 + 255) / 256, 256>>>(logits);
    // Stage 2: main reduction
    concrete_selector_kernel<<<N_, 1024>>>(x, u, out);
}